// round 13
// baseline (speedup 1.0000x reference)
#include <cuda_runtime.h>
#include <cuda_bf16.h>
#include <cstdint>

#define BINS 256
#define NCOPIES 16          // 2 sub-histograms per warp (selected by lane parity)
#define HIST_BLOCKS 1184    // 148 SMs x 8 blocks -> one wave at occupancy 8
#define HIST_THREADS 256

// Scratch (device globals -> no allocation). Zero-initialized at module load;
// the last block resets them every launch, so every graph replay starts clean.
__device__ unsigned int g_hist[BINS];
__device__ unsigned int g_ticket;

__device__ __forceinline__ void bin_one(float x, unsigned int* hist) {
    // torch.histc over [-4,4]: x==4 -> last bin; outside/NaN ignored.
    // |x|<=4 is one FSETP (free |x| mod); fmaf(x,32,128)==round((x+4)*32)
    // bit-exact (power-of-2 scale commutes with rounding).
    if (fabsf(x) <= 4.0f) {
        float t = fmaf(x, 32.0f, 128.0f);
        int idx = __float2int_rd(t);
        idx = min(idx, BINS - 1);
        atomicAdd(&hist[idx], 1u);
    }
}

__device__ __forceinline__ void bin4(float4 v, unsigned int* h) {
    bin_one(v.x, h);
    bin_one(v.y, h);
    bin_one(v.z, h);
    bin_one(v.w, h);
}

__global__ void __launch_bounds__(HIST_THREADS, 8)
hist_kernel(const float* __restrict__ x, long long n,
            float* __restrict__ out, int out_size) {
    __shared__ unsigned int sh[NCOPIES][BINS];
    __shared__ bool is_last;
    const int tid  = threadIdx.x;
    const int warp = tid >> 5;
    const int lane = tid & 31;
    unsigned int* wh = sh[(warp << 1) | (lane & 1)];

    #pragma unroll
    for (int i = tid; i < NCOPIES * BINS; i += HIST_THREADS)
        ((unsigned int*)sh)[i] = 0u;
    __syncthreads();

    const long long n4 = n >> 2;
    const float4* __restrict__ x4 = (const float4*)x;

    // Blocked-contiguous assignment: block b owns float4s [b*chunk, (b+1)*chunk).
    // Threads stride by 256 inside the chunk, so each block streams its region
    // sequentially (4 KB per block-iteration) -> DRAM row-buffer friendly,
    // unlike grid-stride whose warp accesses jump 4.85 MB every iteration.
    const long long chunk = (n4 + (long long)gridDim.x - 1) / gridDim.x;
    const long long cbeg  = (long long)blockIdx.x * chunk;
    const long long cend  = min(cbeg + chunk, n4);
    const long long stride = HIST_THREADS;

    long long i = cbeg + tid;

    // R7's rolling depth-2 pipeline: bin 2 tiles while the next 2 loads fly.
    if (i + stride < cend) {
        float4 a = __ldcg(x4 + i);
        float4 b = __ldcg(x4 + i + stride);
        long long j = i + 2 * stride;
        for (; j + stride < cend; j += 2 * stride) {
            float4 c = __ldcg(x4 + j);
            float4 d = __ldcg(x4 + j + stride);
            bin4(a, wh);
            bin4(b, wh);
            a = c;
            b = d;
        }
        bin4(a, wh);
        bin4(b, wh);
        i = j;
    }
    // Per-thread remainder inside the chunk
    for (; i < cend; i += stride)
        bin4(__ldcg(x4 + i), wh);

    // Scalar tail (n not multiple of 4) — block 0 only.
    if (blockIdx.x == 0) {
        for (long long j = (n4 << 2) + tid; j < n; j += HIST_THREADS)
            bin_one(x[j], wh);
    }
    __syncthreads();

    // Reduce the copies, one gmem atomic per bin per block.
    for (int b = tid; b < BINS; b += HIST_THREADS) {
        unsigned int s = 0;
        #pragma unroll
        for (int c = 0; c < NCOPIES; c++) s += sh[c][b];
        if (s) atomicAdd(&g_hist[b], s);
    }

    // Last-block finalize: write output, reset globals for next graph replay.
    __threadfence();
    __syncthreads();
    if (tid == 0)
        is_last = (atomicAdd(&g_ticket, 1u) == (unsigned)gridDim.x - 1u);
    __syncthreads();

    if (is_last) {
        __threadfence();
        unsigned int v = g_hist[tid];
        g_hist[tid] = 0u;
        if (tid == 0) g_ticket = 0u;
        float fv = (float)v;
        for (int base = 0; base + tid < out_size; base += BINS)
            out[base + tid] = fv;   // reference returns (h, h)
    }
}

extern "C" void kernel_launch(void* const* d_in, const int* in_sizes, int n_in,
                              void* d_out, int out_size) {
    const float* x = (const float*)d_in[0];
    long long n = (long long)in_sizes[0];
    float* out = (float*)d_out;

    hist_kernel<<<HIST_BLOCKS, HIST_THREADS>>>(x, n, out, out_size);
}